// round 11
// baseline (speedup 1.0000x reference)
#include <cuda_runtime.h>
#include <math.h>

#define N_   512
#define M_   2048
#define C_   256
#define KTOP 6

typedef unsigned long long ull;

// Scratch (static __device__ globals: allocation-free per harness rules)
__device__ float g_anti[2][N_ * M_];   // split-K partials
__device__ float g_rowco[N_];
__device__ int   g_cnt = 0;

// ---- packed f32x2 helpers (FFMA2: 2 FMA per instruction on sm_103a) -------
__device__ __forceinline__ ull pack2(float x) {
    ull r; asm("mov.b64 %0, {%1, %1};" : "=l"(r) : "f"(x)); return r;
}
__device__ __forceinline__ void fma2(ull& d, ull a, ull b) {
    asm("fma.rn.f32x2 %0, %1, %2, %0;" : "+l"(d) : "l"(a), "l"(b));
}
__device__ __forceinline__ void unpack2(ull v, float& lo, float& hi) {
    asm("mov.b64 {%0, %1}, %2;" : "=f"(lo), "=f"(hi) : "l"(v));
}

// ---------------------------------------------------------------------------
// Kernel 1 (UNCHANGED from R8 — measured ~17.5us):
// partial_z[n,m] = Aq_z[m] - 2 * dot_z(w'*micro[n], micro_all[m])
//   w'[c] = fc_w[c] - 1/C ; Aq_z over this block's K-half.
//   (per-row Bq[n] dropped: row-constant -> invariant for top-k + exp weights)
// Tile 128(m) x 64(n) x Khalf(128), 128 threads, 8x8 frag, TK=16, double-buf.
// grid (16, 8, 2) = 256 blocks -> 2 CTAs/SM.
// ---------------------------------------------------------------------------
#define TMm 128
#define TNn 64
#define TK  16
#define KHALF 128

__global__ void __launch_bounds__(128, 2)
anti_gemm(const float* __restrict__ micro,
          const float* __restrict__ micro_all,
          const float* __restrict__ fc_w) {
    __shared__ float As[2][TK][TNn + 4];     // As[k][n] = w'[k]*micro[n,k]
    __shared__ float Bs[2][TK][TMm + 4];     // Bs[k][m] = micro_all[m,k]
    __shared__ float sw[C_];                 // w'
    __shared__ float sAqP[TMm * 4];          // Aq partials [m_local*4 + kgrp]

    const int tid = threadIdx.x;
    const int m0 = blockIdx.x * TMm;
    const int n0 = blockIdx.y * TNn;
    const int z  = blockIdx.z;
    const int kb = z * KHALF;

    sw[tid]       = fc_w[tid]       - (1.0f / (float)C_);
    sw[tid + 128] = fc_w[tid + 128] - (1.0f / (float)C_);
    __syncthreads();

    const int lr  = tid >> 2;           // 0..31 loader row slot
    const int lkp = (tid & 3) << 2;     // k sub-offset 0,4,8,12
    const int tx  = tid & 15;           // m frag group (8 cols)
    const int ty  = tid >> 4;           // n frag group (8 rows), 0..7

    float4 pb[4], pa[2];
    float  aqp[4] = {0.f, 0.f, 0.f, 0.f};
    ull    acc[8][4];
    #pragma unroll
    for (int i = 0; i < 8; i++)
        #pragma unroll
        for (int j = 0; j < 4; j++) acc[i][j] = 0ull;

    auto LOAD = [&](int k0) {           // k0 global
        #pragma unroll
        for (int i = 0; i < 4; i++)
            pb[i] = *(const float4*)&micro_all[(m0 + lr + 32 * i) * C_ + k0 + lkp];
        #pragma unroll
        for (int i = 0; i < 2; i++)
            pa[i] = *(const float4*)&micro[(n0 + lr + 32 * i) * C_ + k0 + lkp];
    };
    auto STORE = [&](int buf, int k0) {
        float4 w4 = *(const float4*)&sw[k0 + lkp];
        #pragma unroll
        for (int i = 0; i < 4; i++) {
            int r = lr + 32 * i;
            Bs[buf][lkp + 0][r] = pb[i].x;
            Bs[buf][lkp + 1][r] = pb[i].y;
            Bs[buf][lkp + 2][r] = pb[i].z;
            Bs[buf][lkp + 3][r] = pb[i].w;
            aqp[i] += w4.x * pb[i].x * pb[i].x + w4.y * pb[i].y * pb[i].y
                    + w4.z * pb[i].z * pb[i].z + w4.w * pb[i].w * pb[i].w;
        }
        #pragma unroll
        for (int i = 0; i < 2; i++) {
            int r = lr + 32 * i;
            As[buf][lkp + 0][r] = w4.x * pa[i].x;
            As[buf][lkp + 1][r] = w4.y * pa[i].y;
            As[buf][lkp + 2][r] = w4.z * pa[i].z;
            As[buf][lkp + 3][r] = w4.w * pa[i].w;
        }
    };

    LOAD(kb);
    STORE(0, kb);
    __syncthreads();

    #pragma unroll 1
    for (int c = 0; c < KHALF / TK; c++) {
        if (c < KHALF / TK - 1) LOAD(kb + (c + 1) * TK);
        const int buf = c & 1;
        #pragma unroll
        for (int k = 0; k < TK; k++) {
            float4 a0 = *(const float4*)&As[buf][k][ty * 8];
            float4 a1 = *(const float4*)&As[buf][k][ty * 8 + 4];
            ulonglong2 b0 = *(const ulonglong2*)&Bs[buf][k][tx * 8];
            ulonglong2 b1 = *(const ulonglong2*)&Bs[buf][k][tx * 8 + 4];
            ull bb0 = b0.x, bb1 = b0.y, bb2 = b1.x, bb3 = b1.y;
            float av[8] = {a0.x, a0.y, a0.z, a0.w, a1.x, a1.y, a1.z, a1.w};
            #pragma unroll
            for (int i = 0; i < 8; i++) {
                ull aa = pack2(av[i]);
                fma2(acc[i][0], aa, bb0);
                fma2(acc[i][1], aa, bb1);
                fma2(acc[i][2], aa, bb2);
                fma2(acc[i][3], aa, bb3);
            }
        }
        if (c < KHALF / TK - 1) {
            STORE((c + 1) & 1, kb + (c + 1) * TK);
            __syncthreads();
        }
    }

    // Aq partials: slot (m_local*4 + kgrp) == tid + 128*i by construction
    #pragma unroll
    for (int i = 0; i < 4; i++) sAqP[tid + 128 * i] = aqp[i];
    __syncthreads();

    float aqv[8];
    #pragma unroll
    for (int t = 0; t < 8; t++) {
        float4 q = *(const float4*)&sAqP[(tx * 8 + t) * 4];
        aqv[t] = (q.x + q.y) + (q.z + q.w);
    }

    float* base = &g_anti[z][0];
    #pragma unroll
    for (int i = 0; i < 8; i++) {
        int n = n0 + ty * 8 + i;
        float lo0, hi0, lo1, hi1;
        unpack2(acc[i][0], lo0, hi0);
        unpack2(acc[i][1], lo1, hi1);
        float4 o0 = make_float4(aqv[0] - 2.f * lo0, aqv[1] - 2.f * hi0,
                                aqv[2] - 2.f * lo1, aqv[3] - 2.f * hi1);
        unpack2(acc[i][2], lo0, hi0);
        unpack2(acc[i][3], lo1, hi1);
        float4 o1 = make_float4(aqv[4] - 2.f * lo0, aqv[5] - 2.f * hi0,
                                aqv[6] - 2.f * lo1, aqv[7] - 2.f * hi1);
        float* dst = &base[n * M_ + m0 + tx * 8];
        *(float4*)&dst[0] = o0;
        *(float4*)&dst[4] = o1;
    }
}

// ---------------------------------------------------------------------------
// Kernel 2 (rewritten for occupancy): 512 threads (16 warps) per row; each
// lane holds only 4 contiguous columns -> 8192 warps total (~86% occ cap vs
// 43% before). Each warp finds top-6 of its 128-col segment (exact lax.top_k
// tie-break), warp 0 merges the 96 candidates, weights + output row + co,
// deterministic last-block co_loss.
// ---------------------------------------------------------------------------
__global__ void __launch_bounds__(512)
topk_kernel(const float* __restrict__ micro,
            const float* __restrict__ micro_all,
            const float* __restrict__ label,
            const float* __restrict__ label_all,
            float* __restrict__ out, int out_size) {
    const int tid  = threadIdx.x;
    const int lane = tid & 31;
    const int w    = tid >> 5;            // 0..15
    const int n    = blockIdx.x;
    const int base = w * 128 + lane * 4;  // this lane's 4 contiguous columns

    const float* r0 = &g_anti[0][n * M_];
    const float* r1 = &g_anti[1][n * M_];
    float4 p0 = *(const float4*)&r0[base];
    float4 q0 = *(const float4*)&r1[base];
    float v[4] = {p0.x + q0.x, p0.y + q0.y, p0.z + q0.z, p0.w + q0.w};

    __shared__ float sv[16 * KTOP];
    __shared__ int   si[16 * KTOP];
    __shared__ float swgt[KTOP];
    __shared__ int   sgix[KTOP];
    __shared__ float co6[KTOP];

    #pragma unroll
    for (int it = 0; it < KTOP; it++) {
        float best = v[0]; int bj = 0;
        #pragma unroll
        for (int e = 1; e < 4; e++)
            if (v[e] > best) { best = v[e]; bj = e; }   // ascending e: lowest idx
        int bi = base + bj;
        #pragma unroll
        for (int s = 16; s; s >>= 1) {
            float ov = __shfl_xor_sync(0xffffffffu, best, s);
            int   oi = __shfl_xor_sync(0xffffffffu, bi, s);
            if (ov > best || (ov == best && oi < bi)) { best = ov; bi = oi; }
        }
        int rel = bi - base;               // 0..3 only for the owning lane
        #pragma unroll
        for (int e = 0; e < 4; e++)
            if (e == rel) v[e] = -INFINITY;
        if (lane == 0) { sv[w * KTOP + it] = best; si[w * KTOP + it] = bi; }
    }
    __syncthreads();

    if (w == 0) {
        // merge 96 candidates (3 per lane; indices globally unique)
        float cv[3]; int ci[3];
        #pragma unroll
        for (int t = 0; t < 3; t++) { cv[t] = sv[lane + 32 * t]; ci[t] = si[lane + 32 * t]; }
        float fv[KTOP]; int fi[KTOP];
        #pragma unroll
        for (int it = 0; it < KTOP; it++) {
            float best = cv[0]; int bi = ci[0];
            #pragma unroll
            for (int t = 1; t < 3; t++)
                if (cv[t] > best || (cv[t] == best && ci[t] < bi)) { best = cv[t]; bi = ci[t]; }
            #pragma unroll
            for (int s = 16; s; s >>= 1) {
                float ov = __shfl_xor_sync(0xffffffffu, best, s);
                int   oi = __shfl_xor_sync(0xffffffffu, bi, s);
                if (ov > best || (ov == best && oi < bi)) { best = ov; bi = oi; }
            }
            fv[it] = best; fi[it] = bi;
            #pragma unroll
            for (int t = 0; t < 3; t++)
                if (ci[t] == bi) cv[t] = -INFINITY;
        }
        if (lane == 0) {
            float e[KTOP], s = 0.f;
            #pragma unroll
            for (int k = 0; k < KTOP; k++) { e[k] = expf(fv[k] - fv[0]); s += e[k]; }
            float inv = 1.f / s;
            #pragma unroll
            for (int k = 0; k < KTOP; k++) { swgt[k] = e[k] * inv; sgix[k] = fi[k]; }
        }
    }
    __syncthreads();

    if (tid < KTOP)
        co6[tid] = swgt[tid] * fabsf(label_all[sgix[tid]] - label[n]);

    // micro_tmp[n,:] = micro[n,:] + sum_k cut_k * micro_all[idx_k,:]
    if (tid < C_) {
        float o = micro[n * C_ + tid];
        #pragma unroll
        for (int k = 0; k < KTOP; k++)
            o += swgt[k] * micro_all[sgix[k] * C_ + tid];
        out[n * C_ + tid] = o;
    }
    __syncthreads();

    if (tid == 0)
        g_rowco[n] = ((co6[0] + co6[1]) + (co6[2] + co6[3])) + (co6[4] + co6[5]);

    // deterministic co_loss: last arriving block does a fixed-order tree
    __threadfence();
    __syncthreads();
    __shared__ int isLast;
    if (tid == 0)
        isLast = (atomicAdd(&g_cnt, 1) == (int)gridDim.x - 1);
    __syncthreads();
    if (isLast) {
        __shared__ float red[256];
        if (tid < 256) red[tid] = g_rowco[tid] + g_rowco[tid + 256];
        __syncthreads();
        #pragma unroll
        for (int s2 = 128; s2 > 0; s2 >>= 1) {
            if (tid < s2) red[tid] += red[tid + s2];
            __syncthreads();
        }
        if (tid == 0) {
            if (out_size > N_ * C_)
                out[N_ * C_] = 1e-4f + red[0] / (float)N_;
            g_cnt = 0;   // reset for graph replays
        }
    }
}

// ---------------------------------------------------------------------------
extern "C" void kernel_launch(void* const* d_in, const int* in_sizes, int n_in,
                              void* d_out, int out_size) {
    const float* micro     = (const float*)d_in[0];   // [512, 256]
    const float* label     = (const float*)d_in[1];   // [512]
    const float* micro_all = (const float*)d_in[2];   // [2048, 256]
    const float* label_all = (const float*)d_in[3];   // [2048]
    const float* fc_w      = (const float*)d_in[4];   // [256]
    float* out = (float*)d_out;

    anti_gemm<<<dim3(M_ / TMm, N_ / TNn, 2), 128>>>(micro, micro_all, fc_w);
    topk_kernel<<<N_, 512>>>(micro, micro_all, label, label_all, out, out_size);
}

// round 12
// speedup vs baseline: 1.0297x; 1.0297x over previous
#include <cuda_runtime.h>
#include <math.h>

#define N_   512
#define M_   2048
#define C_   256
#define KTOP 6

#define TMm 128
#define TNn 64
#define TK  16
#define MTILES (M_ / TMm)              // 16

typedef unsigned long long ull;
typedef unsigned int u32;

// Scratch (static __device__ globals: allocation-free per harness rules)
__device__ ull   g_cand[N_][MTILES * KTOP];   // packed (ord(val)<<32 | ~col)
__device__ float g_rowco[N_];
__device__ int   g_cnt = 0;

// ---- packed f32x2 helpers (FFMA2: 2 FMA per instruction on sm_103a) -------
__device__ __forceinline__ ull pack2(float x) {
    ull r; asm("mov.b64 %0, {%1, %1};" : "=l"(r) : "f"(x)); return r;
}
__device__ __forceinline__ void fma2(ull& d, ull a, ull b) {
    asm("fma.rn.f32x2 %0, %1, %2, %0;" : "+l"(d) : "l"(a), "l"(b));
}
__device__ __forceinline__ void unpack2(ull v, float& lo, float& hi) {
    asm("mov.b64 {%0, %1}, %2;" : "=f"(lo), "=f"(hi) : "l"(v));
}

// ---- order-preserving float <-> u32 (monotone under unsigned compare) -----
__device__ __forceinline__ u32 ordf(float v) {
    u32 s = __float_as_uint(v);
    return s ^ (u32)(((int)s >> 31) | 0x80000000);
}
__device__ __forceinline__ float deordf(u32 o) {
    u32 s = (o & 0x80000000u) ? (o ^ 0x80000000u) : ~o;
    return __uint_as_float(s);
}

// ---------------------------------------------------------------------------
// Kernel 1: full-K anti tile + candidate epilogue.
//   anti[n,m] = Aq[m] - 2 * dot(w'*micro[n], micro_all[m])
//   w'[c] = fc_w[c] - 1/C (folds dis.mean); per-row Bq[n] dropped (row-const,
//   invariant for top-k selection and exp(anti - rowmax) weights).
// Mainloop IDENTICAL to the measured-good R8 loop (TM128/TN64/TK16, 128 thr,
// 8x8 ull frags, double-buffered smem), K = 256 in one block.
// Epilogue: per-row top-6 of this 128-col m-tile via u64 keys
//   key = ord(val)<<32 | ~col  ->  max == (val desc, col asc) exactly.
// Per-tile top-6 is sufficient for global top-6 (>=6 in-tile beaters
// imply >=6 global beaters). Writes 6 keys per (row, m-tile) -> g_cand.
// ---------------------------------------------------------------------------
__global__ void __launch_bounds__(128, 2)
anti_gemm(const float* __restrict__ micro,
          const float* __restrict__ micro_all,
          const float* __restrict__ fc_w) {
    __shared__ float As[2][TK][TNn + 4];     // As[k][n] = w'[k]*micro[n,k]
    __shared__ float Bs[2][TK][TMm + 4];     // Bs[k][m] = micro_all[m,k]
    __shared__ float sw[C_];                 // w'
    __shared__ float sAqP[TMm * 4];          // Aq partials [m_local*4 + kgrp]

    const int tid = threadIdx.x;
    const int m0 = blockIdx.x * TMm;
    const int n0 = blockIdx.y * TNn;

    sw[tid]       = fc_w[tid]       - (1.0f / (float)C_);
    sw[tid + 128] = fc_w[tid + 128] - (1.0f / (float)C_);
    __syncthreads();

    const int lr  = tid >> 2;           // 0..31 loader row slot
    const int lkp = (tid & 3) << 2;     // k sub-offset 0,4,8,12
    const int tx  = tid & 15;           // m frag group (8 cols)
    const int ty  = tid >> 4;           // n frag group (8 rows), 0..7

    float4 pb[4], pa[2];
    float  aqp[4] = {0.f, 0.f, 0.f, 0.f};
    ull    acc[8][4];
    #pragma unroll
    for (int i = 0; i < 8; i++)
        #pragma unroll
        for (int j = 0; j < 4; j++) acc[i][j] = 0ull;

    auto LOAD = [&](int k0) {
        #pragma unroll
        for (int i = 0; i < 4; i++)
            pb[i] = *(const float4*)&micro_all[(m0 + lr + 32 * i) * C_ + k0 + lkp];
        #pragma unroll
        for (int i = 0; i < 2; i++)
            pa[i] = *(const float4*)&micro[(n0 + lr + 32 * i) * C_ + k0 + lkp];
    };
    auto STORE = [&](int buf, int k0) {
        float4 w4 = *(const float4*)&sw[k0 + lkp];
        #pragma unroll
        for (int i = 0; i < 4; i++) {
            int r = lr + 32 * i;
            Bs[buf][lkp + 0][r] = pb[i].x;
            Bs[buf][lkp + 1][r] = pb[i].y;
            Bs[buf][lkp + 2][r] = pb[i].z;
            Bs[buf][lkp + 3][r] = pb[i].w;
            aqp[i] += w4.x * pb[i].x * pb[i].x + w4.y * pb[i].y * pb[i].y
                    + w4.z * pb[i].z * pb[i].z + w4.w * pb[i].w * pb[i].w;
        }
        #pragma unroll
        for (int i = 0; i < 2; i++) {
            int r = lr + 32 * i;
            As[buf][lkp + 0][r] = w4.x * pa[i].x;
            As[buf][lkp + 1][r] = w4.y * pa[i].y;
            As[buf][lkp + 2][r] = w4.z * pa[i].z;
            As[buf][lkp + 3][r] = w4.w * pa[i].w;
        }
    };

    LOAD(0);
    STORE(0, 0);
    __syncthreads();

    #pragma unroll 1
    for (int c = 0; c < C_ / TK; c++) {
        if (c < C_ / TK - 1) LOAD((c + 1) * TK);
        const int buf = c & 1;
        #pragma unroll
        for (int k = 0; k < TK; k++) {
            float4 a0 = *(const float4*)&As[buf][k][ty * 8];
            float4 a1 = *(const float4*)&As[buf][k][ty * 8 + 4];
            ulonglong2 b0 = *(const ulonglong2*)&Bs[buf][k][tx * 8];
            ulonglong2 b1 = *(const ulonglong2*)&Bs[buf][k][tx * 8 + 4];
            ull bb0 = b0.x, bb1 = b0.y, bb2 = b1.x, bb3 = b1.y;
            float av[8] = {a0.x, a0.y, a0.z, a0.w, a1.x, a1.y, a1.z, a1.w};
            #pragma unroll
            for (int i = 0; i < 8; i++) {
                ull aa = pack2(av[i]);
                fma2(acc[i][0], aa, bb0);
                fma2(acc[i][1], aa, bb1);
                fma2(acc[i][2], aa, bb2);
                fma2(acc[i][3], aa, bb3);
            }
        }
        if (c < C_ / TK - 1) {
            STORE((c + 1) & 1, (c + 1) * TK);
            __syncthreads();
        }
    }

    // Aq partials: slot (m_local*4 + kgrp) == tid + 128*i by construction
    #pragma unroll
    for (int i = 0; i < 4; i++) sAqP[tid + 128 * i] = aqp[i];
    __syncthreads();

    float aqv[8];
    #pragma unroll
    for (int t = 0; t < 8; t++) {
        float4 q = *(const float4*)&sAqP[(tx * 8 + t) * 4];
        aqv[t] = (q.x + q.y) + (q.z + q.w);
    }

    // ---- candidate epilogue: per-row top-6 of this 128-col tile ----
    // Row n is owned by the 16 lanes sharing ty (lanes 0-15 or 16-31 of a
    // warp); shfl_xor s=1,2,4,8 reduces within that 16-lane group.
    #pragma unroll
    for (int i = 0; i < 8; i++) {
        const int n = n0 + ty * 8 + i;
        ull key[8];
        #pragma unroll
        for (int jj = 0; jj < 4; jj++) {
            float lo, hi;
            unpack2(acc[i][jj], lo, hi);
            float v0 = aqv[2 * jj]     - 2.f * lo;
            float v1 = aqv[2 * jj + 1] - 2.f * hi;
            int c0 = m0 + tx * 8 + 2 * jj;
            key[2 * jj]     = ((ull)ordf(v0) << 32) | (u32)(~c0);
            key[2 * jj + 1] = ((ull)ordf(v1) << 32) | (u32)(~(c0 + 1));
        }
        #pragma unroll
        for (int it = 0; it < KTOP; it++) {
            // branchless tree max over the 8 local keys
            ull m01 = key[0] > key[1] ? key[0] : key[1];
            ull m23 = key[2] > key[3] ? key[2] : key[3];
            ull m45 = key[4] > key[5] ? key[4] : key[5];
            ull m67 = key[6] > key[7] ? key[6] : key[7];
            ull m03 = m01 > m23 ? m01 : m23;
            ull m47 = m45 > m67 ? m45 : m67;
            ull kb  = m03 > m47 ? m03 : m47;
            #pragma unroll
            for (int s = 1; s < 16; s <<= 1) {
                ull o = __shfl_xor_sync(0xffffffffu, kb, s);
                if (o > kb) kb = o;
            }
            if (tx == 0)
                g_cand[n][blockIdx.x * KTOP + it] = kb;
            // owner removes the winner (keys globally unique via ~col)
            int rel = (int)(~(u32)kb) - (m0 + tx * 8);
            #pragma unroll
            for (int e = 0; e < 8; e++)
                if (e == rel) key[e] = 0ull;
        }
    }
}

// ---------------------------------------------------------------------------
// Kernel 2: one block (128 thr) per row. Warp 0 merges the 96 tile candidates
// (u64 key max == exact lax.top_k order; keys globally unique), lane 0 builds
// exp weights over the top-6 (full softmax denominator cancels analytically),
// block writes the output row; deterministic last-block co_loss reduction.
// ---------------------------------------------------------------------------
__global__ void __launch_bounds__(128)
merge_kernel(const float* __restrict__ micro,
             const float* __restrict__ micro_all,
             const float* __restrict__ label,
             const float* __restrict__ label_all,
             float* __restrict__ out, int out_size) {
    const int tid  = threadIdx.x;
    const int lane = tid & 31;
    const int n    = blockIdx.x;

    __shared__ float swgt[KTOP];
    __shared__ int   sgix[KTOP];
    __shared__ float co6[KTOP];

    if (tid < 32) {
        const ull* cp = &g_cand[n][0];
        ull c0 = cp[lane], c1 = cp[lane + 32], c2 = cp[lane + 64];
        float fv[KTOP]; int fi[KTOP];
        #pragma unroll
        for (int it = 0; it < KTOP; it++) {
            ull b01 = c0 > c1 ? c0 : c1;
            ull kb  = b01 > c2 ? b01 : c2;
            #pragma unroll
            for (int s = 16; s; s >>= 1) {
                ull o = __shfl_xor_sync(0xffffffffu, kb, s);
                if (o > kb) kb = o;
            }
            fv[it] = deordf((u32)(kb >> 32));
            fi[it] = (int)(~(u32)kb) & 0x7fffffff;
            if (c0 == kb) c0 = 0ull;
            if (c1 == kb) c1 = 0ull;
            if (c2 == kb) c2 = 0ull;
        }
        if (lane == 0) {
            float e[KTOP], s = 0.f;
            #pragma unroll
            for (int k = 0; k < KTOP; k++) { e[k] = expf(fv[k] - fv[0]); s += e[k]; }
            float inv = 1.f / s;
            #pragma unroll
            for (int k = 0; k < KTOP; k++) { swgt[k] = e[k] * inv; sgix[k] = fi[k]; }
        }
    }
    __syncthreads();

    if (tid < KTOP)
        co6[tid] = swgt[tid] * fabsf(label_all[sgix[tid]] - label[n]);

    // micro_tmp[n,:] = micro[n,:] + sum_k cut_k * micro_all[idx_k,:]
    #pragma unroll
    for (int jj = 0; jj < C_ / 128; jj++) {
        int c = tid + 128 * jj;
        float o = micro[n * C_ + c];
        #pragma unroll
        for (int k = 0; k < KTOP; k++)
            o += swgt[k] * micro_all[sgix[k] * C_ + c];
        out[n * C_ + c] = o;
    }
    __syncthreads();

    if (tid == 0)
        g_rowco[n] = ((co6[0] + co6[1]) + (co6[2] + co6[3])) + (co6[4] + co6[5]);

    // deterministic co_loss: last arriving block does a fixed-order tree
    __threadfence();
    __syncthreads();
    __shared__ int isLast;
    if (tid == 0)
        isLast = (atomicAdd(&g_cnt, 1) == (int)gridDim.x - 1);
    __syncthreads();
    if (isLast) {
        __shared__ float red[128];
        red[tid] = (g_rowco[tid] + g_rowco[tid + 128])
                 + (g_rowco[tid + 256] + g_rowco[tid + 384]);
        __syncthreads();
        #pragma unroll
        for (int s2 = 64; s2 > 0; s2 >>= 1) {
            if (tid < s2) red[tid] += red[tid + s2];
            __syncthreads();
        }
        if (tid == 0) {
            if (out_size > N_ * C_)
                out[N_ * C_] = 1e-4f + red[0] / (float)N_;
            g_cnt = 0;   // reset for graph replays
        }
    }
}

// ---------------------------------------------------------------------------
extern "C" void kernel_launch(void* const* d_in, const int* in_sizes, int n_in,
                              void* d_out, int out_size) {
    const float* micro     = (const float*)d_in[0];   // [512, 256]
    const float* label     = (const float*)d_in[1];   // [512]
    const float* micro_all = (const float*)d_in[2];   // [2048, 256]
    const float* label_all = (const float*)d_in[3];   // [2048]
    const float* fc_w      = (const float*)d_in[4];   // [256]
    float* out = (float*)d_out;

    anti_gemm<<<dim3(M_ / TMm, N_ / TNn), 128>>>(micro, micro_all, fc_w);
    merge_kernel<<<N_, 128>>>(micro, micro_all, label, label_all, out, out_size);
}